// round 15
// baseline (speedup 1.0000x reference)
#include <cuda_runtime.h>
#include <cuda_bf16.h>
#include <math.h>
#include <stdint.h>

#define NT 2
#define NN 50000
#define EE 400000
#define CC 128
#define HH 4
#define DD 32
#define NTILES128 391   // ceil(50000/128)

// ---------------- device scratch (allocation-free: static globals) ----------------
__device__ float g_q  [NT][(size_t)NN*CC];
__device__ float g_k  [NT][(size_t)NN*CC];
__device__ float g_v  [NT][(size_t)NN*CC];
__device__ float g_agg[NT][(size_t)NN*CC];   // UNNORMALIZED sum of a*v
__device__ float g_xb [NT][(size_t)NN*CC];   // layer output ping buffer
__device__ float g_den[NT][(size_t)NN*HH];
// CSR by destination, per edge type (built once per call)
__device__ int g_off[NT][NN + 1];
__device__ int g_csr[NT][EE];
__device__ int g_cnt[NT][NN];
// W in mma B-fragment order, BOTH layers: widx = l*8 + (t*3+{Q,K,V} | 6+t for Wa)
__device__ uint4 g_Wf  [16][4096];
__device__ float g_bias[16][CC];

// ---------------- small helpers ----------------------------------------------------
__device__ __forceinline__ int lane_id() { return threadIdx.x & 31; }

__device__ __forceinline__ uint32_t smem_u32(const void* p) {
    uint32_t a;
    asm("{ .reg .u64 t; cvta.to.shared.u64 t, %1; cvt.u32.u64 %0, t; }" : "=r"(a) : "l"(p));
    return a;
}
// gelu(tanh approx) == v * sigmoid(2c(v + 0.044715 v^3)) — exact identity, MUFU-cheap
__device__ __forceinline__ float gelu_fast(float v) {
    float z = 1.5957691216057308f * (v + 0.044715f * v * v * v);
    return __fdividef(v, 1.0f + __expf(-z));
}
// split two floats into packed bf16x2 hi and lo words (elem0 in low half)
__device__ __forceinline__ void split2(float v0, float v1, uint32_t& hi, uint32_t& lo) {
    __nv_bfloat16 h0 = __float2bfloat16_rn(v0), h1 = __float2bfloat16_rn(v1);
    __nv_bfloat16 l0 = __float2bfloat16_rn(v0 - __bfloat162float(h0));
    __nv_bfloat16 l1 = __float2bfloat16_rn(v1 - __bfloat162float(h1));
    __nv_bfloat162 H = __halves2bfloat162(h0, h1);
    __nv_bfloat162 L = __halves2bfloat162(l0, l1);
    hi = *(uint32_t*)&H; lo = *(uint32_t*)&L;
}
__device__ __forceinline__ void mma_bf16(float* d, const uint32_t* a, uint32_t b0, uint32_t b1) {
    asm volatile("mma.sync.aligned.m16n8k16.row.col.f32.bf16.bf16.f32 "
        "{%0,%1,%2,%3}, {%4,%5,%6,%7}, {%8,%9}, {%0,%1,%2,%3};"
        : "+f"(d[0]), "+f"(d[1]), "+f"(d[2]), "+f"(d[3])
        : "r"(a[0]), "r"(a[1]), "r"(a[2]), "r"(a[3]), "r"(b0), "r"(b1));
}
__device__ __forceinline__ void ldsm4(uint32_t* r, uint32_t addr) {
    asm volatile("ldmatrix.sync.aligned.m8n8.x4.shared.b16 {%0,%1,%2,%3}, [%4];"
        : "=r"(r[0]), "=r"(r[1]), "=r"(r[2]), "=r"(r[3]) : "r"(addr));
}

// ---------------- prep: fold + split + fragment-order weights (both layers) --------
// grid (t=2, which=4, 16 = l*8 + ks). 128 threads.
__global__ void prep_weights(const float* __restrict__ Wk, const float* __restrict__ bk,
                             const float* __restrict__ Wv, const float* __restrict__ bv,
                             const float* __restrict__ Wq, const float* __restrict__ bq,
                             const float* __restrict__ Wa, const float* __restrict__ ba,
                             const float* __restrict__ a_rel, const float* __restrict__ m_rel,
                             const float* __restrict__ p_rel)
{
    __shared__ float sA[HH * DD * DD];   // 16KB [h][d][f]
    __shared__ float sCol[16][CC];       // 8KB  local k-slice of folded W

    int t = blockIdx.x, which = blockIdx.y;
    int l = blockIdx.z >> 3, ks = blockIdx.z & 7;
    int widx = l * 8 + ((which == 3) ? (6 + t) : (t * 3 + which));
    int n = threadIdx.x;                 // output column
    size_t moff = (size_t)(l * NT + t) * CC * CC;
    size_t boff = (size_t)(l * NT + t) * CC;

    if (which == 0 || which == 3) {
        const float* W = (which == 0 ? Wq : Wa) + moff;
        const float* B = (which == 0 ? bq : ba) + boff;
        #pragma unroll
        for (int kl = 0; kl < 16; kl++)
            sCol[kl][n] = W[(size_t)(ks * 16 + kl) * CC + n];
        if (ks == 0) g_bias[widx][n] = B[n];
    } else {
        const float* W = (which == 1 ? Wk : Wv) + moff;
        const float* B = (which == 1 ? bk : bv) + boff;
        const float* R = (which == 1 ? a_rel : m_rel) + (size_t)(l * NT + t) * (HH * DD * DD);
        for (int i = n; i < HH * DD * DD; i += 128) {
            int h = i >> 10;
            float sc = (which == 1) ? p_rel[(l * NT + t) * HH + h] * 0.17677669529663687f : 1.0f;
            sA[i] = R[i] * sc;
        }
        __syncthreads();
        int h = n >> 5, f = n & 31;
        #pragma unroll
        for (int kl = 0; kl < 16; kl++) {
            int k = ks * 16 + kl;
            const float* wr = W + (size_t)k * CC + h * DD;
            const float* ar = sA + h * DD * DD + f;
            float s = 0.f;
            #pragma unroll 8
            for (int d = 0; d < DD; d++) s += wr[d] * ar[d * DD];
            sCol[kl][n] = s;
        }
        if (ks == 0) {
            const float* br = B + h * DD;
            const float* ar = sA + h * DD * DD + f;
            float s = 0.f;
            #pragma unroll 8
            for (int d = 0; d < DD; d++) s += br[d] * ar[d * DD];
            g_bias[widx][n] = s;
        }
    }
    __syncthreads();

    int l32 = n & 31, quad = n >> 5;
    int g = l32 >> 2, tt = l32 & 3;
    #pragma unroll
    for (int jj = 0; jj < 4; jj++) {
        int j = jj * 4 + quad;
        int col = j * 8 + g;
        int k0 = tt * 2;          // local k within this ks chunk
        uint4 frag;
        uint32_t lo0, lo1;
        split2(sCol[k0][col],     sCol[k0 + 1][col], frag.x, lo0);
        split2(sCol[k0 + 8][col], sCol[k0 + 9][col], frag.y, lo1);
        frag.z = lo0; frag.w = lo1;
        g_Wf[widx][(ks * 16 + j) * 32 + l32] = frag;
    }
}

// ---------------- shared mma core: 128x128x128 tile, X hi/lo in smem, W from L1 ----
// warp tile 32x64: 4 M-warps x 2 N-warps. Each B fragment feeds 6 MMAs.
#define OFF_XHI 0                    // 128 rows * 272B
#define OFF_XLO 34816
#define SMEM_G  69632                // 2 CTAs/SM

__device__ __forceinline__ void mma_tile(uint32_t ah_base, uint32_t al_base,
                                         const uint4* __restrict__ wf, int jbase,
                                         float acc[2][8][4])
{
    #pragma unroll
    for (int mt = 0; mt < 2; mt++)
        #pragma unroll
        for (int nt = 0; nt < 8; nt++)
            #pragma unroll
            for (int r = 0; r < 4; r++) acc[mt][nt][r] = 0.f;
    #pragma unroll
    for (int ks = 0; ks < 8; ks++) {
        uint32_t ah[2][4], al[2][4];
        ldsm4(ah[0], ah_base + ks * 32);
        ldsm4(ah[1], ah_base + 16 * 272 + ks * 32);
        ldsm4(al[0], al_base + ks * 32);
        ldsm4(al[1], al_base + 16 * 272 + ks * 32);
        #pragma unroll
        for (int nt = 0; nt < 8; nt++) {
            uint4 b = __ldg(&wf[(ks * 16 + jbase + nt) * 32 + lane_id()]);
            #pragma unroll
            for (int mt = 0; mt < 2; mt++) {
                mma_bf16(acc[mt][nt], ah[mt], b.x, b.y);   // hi*hi
                mma_bf16(acc[mt][nt], al[mt], b.x, b.y);   // lo*hi
                mma_bf16(acc[mt][nt], ah[mt], b.z, b.w);   // hi*lo
            }
        }
    }
}

// ---------------- QKV GEMM: one matrix per blockIdx.y, BM=128 ----------------------
__global__ void __launch_bounds__(256, 2)
gemm_qkv(const float* __restrict__ Xbase, int l)
{
    extern __shared__ char smem[];
    uint32_t sb = smem_u32(smem);
    int tid = threadIdx.x, wid = tid >> 5, lane = tid & 31;

    int which = blockIdx.y;
    int t = which / 3, mat = which % 3;
    const float* X = Xbase + (size_t)t * NN * CC;
    float* Y = (mat == 0) ? g_q[t] : (mat == 1) ? g_k[t] : g_v[t];
    const uint4* __restrict__ wf = g_Wf[l * 8 + which];
    const float* __restrict__ bias = g_bias[l * 8 + which];
    int row0 = blockIdx.x * 128;

    // load X tile (128 rows), split into bf16 hi/lo padded tiles (row stride 272B)
    {
        uint32_t* xh = (uint32_t*)(smem + OFF_XHI);
        uint32_t* xl = (uint32_t*)(smem + OFF_XLO);
        #pragma unroll
        for (int i = 0; i < 16; i++) {
            int idx = tid + i * 256;          // 0..4095 float4s
            int m = idx >> 5, c4 = (idx & 31) * 4;
            int gm = row0 + m;
            float4 v = make_float4(0.f, 0.f, 0.f, 0.f);
            if (gm < NN) v = *(const float4*)(X + (size_t)gm * CC + c4);
            uint32_t h0, l0, h1, l1;
            split2(v.x, v.y, h0, l0);
            split2(v.z, v.w, h1, l1);
            int off = m * 68 + (c4 >> 1);
            *(uint2*)(xh + off) = make_uint2(h0, h1);
            *(uint2*)(xl + off) = make_uint2(l0, l1);
        }
    }
    __syncthreads();

    int warpM = (wid & 3) * 32;
    int jbase = (wid >> 2) * 8;
    uint32_t xrow = (uint32_t)(warpM + (lane & 15)) * 272 + (uint32_t)(lane >> 4) * 16;
    float acc[2][8][4];
    mma_tile(sb + OFF_XHI + xrow, sb + OFF_XLO + xrow, wf, jbase, acc);

    int g = lane >> 2, tt = lane & 3;
    #pragma unroll
    for (int mt = 0; mt < 2; mt++) {
        int r0 = row0 + warpM + mt * 16 + g;
        #pragma unroll
        for (int nt = 0; nt < 8; nt++) {
            int c = (jbase + nt) * 8 + tt * 2;
            float b0 = __ldg(&bias[c]), b1 = __ldg(&bias[c + 1]);
            if (r0 < NN)
                *(float2*)(Y + (size_t)r0 * CC + c) =
                    make_float2(acc[mt][nt][0] + b0, acc[mt][nt][1] + b1);
            if (r0 + 8 < NN)
                *(float2*)(Y + (size_t)(r0 + 8) * CC + c) =
                    make_float2(acc[mt][nt][2] + b0, acc[mt][nt][3] + b1);
        }
    }
}

// ---------------- fused Wa GEMM + gated skip + LayerNorm + ReLU, BM=128 ------------
__global__ void __launch_bounds__(256, 2)
wa_ln(const float* __restrict__ xin_base, float* __restrict__ dout,
      const float* __restrict__ skip, const float* __restrict__ lng,
      const float* __restrict__ lnb, int l)
{
    extern __shared__ char smem[];
    uint32_t sb = smem_u32(smem);
    int tid = threadIdx.x, wid = tid >> 5, lane = tid & 31;
    int t = blockIdx.y;
    const float* X = g_agg[t];
    const float* den = g_den[t];
    const uint4* __restrict__ wf = g_Wf[l * 8 + 6 + t];
    const float* __restrict__ bias = g_bias[l * 8 + 6 + t];
    int row0 = blockIdx.x * 128;

    {
        uint32_t* xh = (uint32_t*)(smem + OFF_XHI);
        uint32_t* xl = (uint32_t*)(smem + OFF_XLO);
        #pragma unroll
        for (int i = 0; i < 16; i++) {
            int idx = tid + i * 256;
            int m = idx >> 5, c4 = (idx & 31) * 4;
            int gm = row0 + m;
            float4 v = make_float4(0.f, 0.f, 0.f, 0.f);
            if (gm < NN) {
                v = *(const float4*)(X + (size_t)gm * CC + c4);
                float invd = __fdividef(1.f, den[(size_t)gm * HH + (c4 >> 5)] + 1e-16f);
                v.x = gelu_fast(v.x * invd); v.y = gelu_fast(v.y * invd);
                v.z = gelu_fast(v.z * invd); v.w = gelu_fast(v.w * invd);
            }
            uint32_t h0, l0, h1, l1;
            split2(v.x, v.y, h0, l0);
            split2(v.z, v.w, h1, l1);
            int off = m * 68 + (c4 >> 1);
            *(uint2*)(xh + off) = make_uint2(h0, h1);
            *(uint2*)(xl + off) = make_uint2(l0, l1);
        }
    }
    __syncthreads();

    int warpM = (wid & 3) * 32;
    int jbase = (wid >> 2) * 8;
    uint32_t xrow = (uint32_t)(warpM + (lane & 15)) * 272 + (uint32_t)(lane >> 4) * 16;
    float acc[2][8][4];
    mma_tile(sb + OFF_XHI + xrow, sb + OFF_XLO + xrow, wf, jbase, acc);
    __syncthreads();   // all LDSM complete -> smem reusable for o staging

    // stage o = acc + bias into smem [128][128] fp32 (64KB fits the 69.6KB X region)
    float* sO = (float*)smem;
    {
        int g = lane >> 2, tt = lane & 3;
        #pragma unroll
        for (int mt = 0; mt < 2; mt++) {
            int rl = warpM + mt * 16 + g;
            #pragma unroll
            for (int nt = 0; nt < 8; nt++) {
                int c = (jbase + nt) * 8 + tt * 2;
                float b0 = __ldg(&bias[c]), b1 = __ldg(&bias[c + 1]);
                *(float2*)(sO + rl * CC + c)       = make_float2(acc[mt][nt][0] + b0, acc[mt][nt][1] + b1);
                *(float2*)(sO + (rl + 8) * CC + c) = make_float2(acc[mt][nt][2] + b0, acc[mt][nt][3] + b1);
            }
        }
    }
    __syncthreads();

    // per-row: skip-mix + LayerNorm + ReLU (warp per row, 16 rows per warp)
    const float* xin = xin_base + (size_t)t * NN * CC;
    float beta = __fdividef(1.f, 1.f + __expf(-skip[l * NT + t]));
    float4 g4 = ((const float4*)(lng + (size_t)(l * NT + t) * CC))[lane];
    float4 b4 = ((const float4*)(lnb + (size_t)(l * NT + t) * CC))[lane];

    #pragma unroll
    for (int it = 0; it < 16; it++) {
        int rl = wid * 16 + it;
        int gm = row0 + rl;
        if (gm >= NN) break;
        float4 ov = ((const float4*)(sO + rl * CC))[lane];
        float4 xv = ((const float4*)(xin + (size_t)gm * CC))[lane];
        float4 v;
        v.x = beta * ov.x + (1.f - beta) * xv.x;
        v.y = beta * ov.y + (1.f - beta) * xv.y;
        v.z = beta * ov.z + (1.f - beta) * xv.z;
        v.w = beta * ov.w + (1.f - beta) * xv.w;

        float s  = v.x + v.y + v.z + v.w;
        float sq = v.x * v.x + v.y * v.y + v.z * v.z + v.w * v.w;
        #pragma unroll
        for (int m = 16; m; m >>= 1) {
            s  += __shfl_xor_sync(0xffffffffu, s,  m);
            sq += __shfl_xor_sync(0xffffffffu, sq, m);
        }
        float mu  = s * (1.f / 128.f);
        float var = sq * (1.f / 128.f) - mu * mu;
        float inv = rsqrtf(var + 1e-5f);

        float4 y;
        y.x = fmaxf((v.x - mu) * inv * g4.x + b4.x, 0.f);
        y.y = fmaxf((v.y - mu) * inv * g4.y + b4.y, 0.f);
        y.z = fmaxf((v.z - mu) * inv * g4.z + b4.z, 0.f);
        y.w = fmaxf((v.w - mu) * inv * g4.w + b4.w, 0.f);
        ((float4*)(g_xb[t] + (size_t)gm * CC))[lane] = y;
        if (dout != nullptr && t == 0)
            ((float4*)(dout + (size_t)gm * CC))[lane] = y;
    }
}

// ---------------- CSR build (once per call) ----------------------------------------
__global__ void hist_k(const int* __restrict__ ei)
{
    int e = blockIdx.y;
    int id = blockIdx.x * 256 + threadIdx.x;
    if (id >= EE) return;
    int di = ei[(size_t)(e * 2 + 1) * EE + id];
    atomicAdd(&g_cnt[e][di], 1);
}

// one block (1024 threads) per edge type: exclusive scan of g_cnt -> g_off.
// Also resets g_cnt to 0 for the scatter pass (saves a memset launch).
__global__ void scan_k()
{
    const int CH = 49;   // 1024*49 = 50176 >= NN
    int e = blockIdx.x, tid = threadIdx.x;
    int base = tid * CH;
    int s = 0;
    for (int i = 0; i < CH; i++) {
        int idx = base + i;
        if (idx < NN) s += g_cnt[e][idx];
    }
    __shared__ int sm[1024];
    sm[tid] = s;
    __syncthreads();
    for (int off = 1; off < 1024; off <<= 1) {
        int v = (tid >= off) ? sm[tid - off] : 0;
        __syncthreads();
        sm[tid] += v;
        __syncthreads();
    }
    int run = sm[tid] - s;   // exclusive prefix
    for (int i = 0; i < CH; i++) {
        int idx = base + i;
        if (idx < NN) {
            g_off[e][idx] = run;
            run += g_cnt[e][idx];
            g_cnt[e][idx] = 0;
        }
    }
    if (tid == 1023) g_off[e][NN] = EE;
}

__global__ void scatter_k(const int* __restrict__ ei)
{
    int e = blockIdx.y;
    int id = blockIdx.x * 256 + threadIdx.x;
    if (id >= EE) return;
    int si = ei[(size_t)(e * 2 + 0) * EE + id];
    int di = ei[(size_t)(e * 2 + 1) * EE + id];
    int pos = g_off[e][di] + atomicAdd(&g_cnt[e][di], 1);
    g_csr[e][pos] = si;
}

// ---------------- edge aggregation: warp per destination, no atomics ---------------
__global__ void edge_agg_csr()
{
    int e = blockIdx.y, st = e, dt = 1 - e;
    int n = blockIdx.x * 8 + (threadIdx.x >> 5);
    if (n >= NN) return;
    int lane = threadIdx.x & 31;
    int beg = g_off[e][n], end = g_off[e][n + 1];

    float4 qv = ((const float4*)(g_q[dt] + (size_t)n * CC))[lane];
    float4 acc = make_float4(0.f, 0.f, 0.f, 0.f);
    float den = 0.f;

    if (beg < end) {
        int si = g_csr[e][beg];
        float4 kv = ((const float4*)(g_k[st] + (size_t)si * CC))[lane];
        float4 vv = ((const float4*)(g_v[st] + (size_t)si * CC))[lane];
        for (int j = beg; j < end; j++) {
            int sin = (j + 1 < end) ? g_csr[e][j + 1] : si;
            float4 kn = ((const float4*)(g_k[st] + (size_t)sin * CC))[lane];
            float4 vn = ((const float4*)(g_v[st] + (size_t)sin * CC))[lane];
            float s = kv.x * qv.x + kv.y * qv.y + kv.z * qv.z + kv.w * qv.w;
            s += __shfl_xor_sync(0xffffffffu, s, 1);
            s += __shfl_xor_sync(0xffffffffu, s, 2);
            s += __shfl_xor_sync(0xffffffffu, s, 4);
            float a = __expf(s);
            den += a;
            acc.x += a * vv.x; acc.y += a * vv.y;
            acc.z += a * vv.z; acc.w += a * vv.w;
            kv = kn; vv = vn;
        }
    }
    ((float4*)(g_agg[dt] + (size_t)n * CC))[lane] = acc;
    if ((lane & 7) == 0)
        g_den[dt][(size_t)n * HH + (lane >> 3)] = den;
}

// ---------------- host orchestration ------------------------------------------------
extern "C" void kernel_launch(void* const* d_in, const int* in_sizes, int n_in,
                              void* d_out, int out_size)
{
    const float* x     = (const float*)d_in[0];
    const int*   ei    = (const int*)d_in[1];   // int32 on device (JAX x64 disabled)
    const float* Wk    = (const float*)d_in[2];
    const float* bk    = (const float*)d_in[3];
    const float* Wq    = (const float*)d_in[4];
    const float* bq    = (const float*)d_in[5];
    const float* Wv    = (const float*)d_in[6];
    const float* bv    = (const float*)d_in[7];
    const float* Wa    = (const float*)d_in[8];
    const float* ba    = (const float*)d_in[9];
    const float* skip  = (const float*)d_in[10];
    const float* a_rel = (const float*)d_in[11];
    const float* m_rel = (const float*)d_in[12];
    const float* p_rel = (const float*)d_in[13];
    const float* ln_g  = (const float*)d_in[14];
    const float* ln_b  = (const float*)d_in[15];
    float* out = (float*)d_out;

    void *pxb, *pcnt;
    cudaGetSymbolAddress(&pxb,  g_xb);
    cudaGetSymbolAddress(&pcnt, g_cnt);

    cudaFuncSetAttribute(gemm_qkv, cudaFuncAttributeMaxDynamicSharedMemorySize, SMEM_G);
    cudaFuncSetAttribute(wa_ln, cudaFuncAttributeMaxDynamicSharedMemorySize, SMEM_G);

    dim3 qkv_grid(NTILES128, 6);
    dim3 wa_grid(NTILES128, 2);
    dim3 ed_grid((EE + 255) / 256, 2);
    dim3 agg_grid((NN + 7) / 8, 2);

    // ---- CSR build + both layers' weight prep ----
    // Launch order arranged so ncu (-s 5 -c 1) captures gemm_qkv (launch #5):
    // memset(0) prep(1) hist(2) scan(3, also resets cnt) scatter(4) gemm_qkv(5)
    cudaMemsetAsync(pcnt, 0, sizeof(int) * NT * NN);
    prep_weights<<<dim3(2, 4, 16), 128>>>(Wk, bk, Wv, bv, Wq, bq, Wa, ba,
                                          a_rel, m_rel, p_rel);
    hist_k<<<ed_grid, 256>>>(ei);
    scan_k<<<2, 1024>>>();
    scatter_k<<<ed_grid, 256>>>(ei);

    for (int l = 0; l < 2; l++) {
        const float* xin = (l == 0) ? x : (const float*)pxb;

        gemm_qkv<<<qkv_grid, 256, SMEM_G>>>(xin, l);

        edge_agg_csr<<<agg_grid, 256>>>();

        wa_ln<<<wa_grid, 256, SMEM_G>>>(xin, (l == 1) ? out : nullptr,
                                        skip, ln_g, ln_b, l);
    }
}

// round 16
// speedup vs baseline: 1.0904x; 1.0904x over previous
#include <cuda_runtime.h>
#include <cuda_bf16.h>
#include <math.h>
#include <stdint.h>

#define NT 2
#define NN 50000
#define EE 400000
#define CC 128
#define HH 4
#define DD 32
#define NTILES128 391   // ceil(50000/128)

// ---------------- device scratch (allocation-free: static globals) ----------------
__device__ __nv_bfloat16 g_qh[NT][(size_t)NN*CC];   // q in bf16 (logit path only)
__device__ __nv_bfloat16 g_kh[NT][(size_t)NN*CC];   // k_rel in bf16 (logit path only)
__device__ float g_v  [NT][(size_t)NN*CC];
__device__ float g_agg[NT][(size_t)NN*CC];   // UNNORMALIZED sum of a*v
__device__ float g_xb [NT][(size_t)NN*CC];   // layer output ping buffer
__device__ float g_den[NT][(size_t)NN*HH];
// CSR by destination, per edge type (built once per call)
__device__ int g_off[NT][NN + 1];
__device__ int g_csr[NT][EE];
__device__ int g_cnt[NT][NN];
// W in mma B-fragment order, BOTH layers: widx = l*8 + (t*3+{Q,K,V} | 6+t for Wa)
__device__ uint4 g_Wf  [16][4096];
__device__ float g_bias[16][CC];

// ---------------- small helpers ----------------------------------------------------
__device__ __forceinline__ int lane_id() { return threadIdx.x & 31; }

__device__ __forceinline__ uint32_t smem_u32(const void* p) {
    uint32_t a;
    asm("{ .reg .u64 t; cvta.to.shared.u64 t, %1; cvt.u32.u64 %0, t; }" : "=r"(a) : "l"(p));
    return a;
}
// gelu(tanh approx) == v * sigmoid(2c(v + 0.044715 v^3)) — exact identity, MUFU-cheap
__device__ __forceinline__ float gelu_fast(float v) {
    float z = 1.5957691216057308f * (v + 0.044715f * v * v * v);
    return __fdividef(v, 1.0f + __expf(-z));
}
// split two floats into packed bf16x2 hi and lo words (elem0 in low half)
__device__ __forceinline__ void split2(float v0, float v1, uint32_t& hi, uint32_t& lo) {
    __nv_bfloat16 h0 = __float2bfloat16_rn(v0), h1 = __float2bfloat16_rn(v1);
    __nv_bfloat16 l0 = __float2bfloat16_rn(v0 - __bfloat162float(h0));
    __nv_bfloat16 l1 = __float2bfloat16_rn(v1 - __bfloat162float(h1));
    __nv_bfloat162 H = __halves2bfloat162(h0, h1);
    __nv_bfloat162 L = __halves2bfloat162(l0, l1);
    hi = *(uint32_t*)&H; lo = *(uint32_t*)&L;
}
__device__ __forceinline__ uint32_t pack_bf16(float v0, float v1) {
    __nv_bfloat162 h = __halves2bfloat162(__float2bfloat16_rn(v0), __float2bfloat16_rn(v1));
    return *(uint32_t*)&h;
}
__device__ __forceinline__ void mma_bf16(float* d, const uint32_t* a, uint32_t b0, uint32_t b1) {
    asm volatile("mma.sync.aligned.m16n8k16.row.col.f32.bf16.bf16.f32 "
        "{%0,%1,%2,%3}, {%4,%5,%6,%7}, {%8,%9}, {%0,%1,%2,%3};"
        : "+f"(d[0]), "+f"(d[1]), "+f"(d[2]), "+f"(d[3])
        : "r"(a[0]), "r"(a[1]), "r"(a[2]), "r"(a[3]), "r"(b0), "r"(b1));
}
__device__ __forceinline__ void ldsm4(uint32_t* r, uint32_t addr) {
    asm volatile("ldmatrix.sync.aligned.m8n8.x4.shared.b16 {%0,%1,%2,%3}, [%4];"
        : "=r"(r[0]), "=r"(r[1]), "=r"(r[2]), "=r"(r[3]) : "r"(addr));
}

// ---------------- prep: fold + split + fragment-order weights (both layers) --------
// grid (t=2, which=4, 16 = l*8 + ks). 128 threads. Also zeroes g_cnt.
__global__ void prep_weights(const float* __restrict__ Wk, const float* __restrict__ bk,
                             const float* __restrict__ Wv, const float* __restrict__ bv,
                             const float* __restrict__ Wq, const float* __restrict__ bq,
                             const float* __restrict__ Wa, const float* __restrict__ ba,
                             const float* __restrict__ a_rel, const float* __restrict__ m_rel,
                             const float* __restrict__ p_rel)
{
    __shared__ float sA[HH * DD * DD];   // 16KB [h][d][f]
    __shared__ float sCol[16][CC];       // 8KB  local k-slice of folded W

    // zero g_cnt (replaces a memset launch); 128 blocks x 128 threads
    {
        int gtid = (((blockIdx.z * 4) + blockIdx.y) * 2 + blockIdx.x) * 128 + threadIdx.x;
        for (int i = gtid; i < NT * NN; i += 16384) ((int*)g_cnt)[i] = 0;
    }

    int t = blockIdx.x, which = blockIdx.y;
    int l = blockIdx.z >> 3, ks = blockIdx.z & 7;
    int widx = l * 8 + ((which == 3) ? (6 + t) : (t * 3 + which));
    int n = threadIdx.x;                 // output column
    size_t moff = (size_t)(l * NT + t) * CC * CC;
    size_t boff = (size_t)(l * NT + t) * CC;

    if (which == 0 || which == 3) {
        const float* W = (which == 0 ? Wq : Wa) + moff;
        const float* B = (which == 0 ? bq : ba) + boff;
        #pragma unroll
        for (int kl = 0; kl < 16; kl++)
            sCol[kl][n] = W[(size_t)(ks * 16 + kl) * CC + n];
        if (ks == 0) g_bias[widx][n] = B[n];
    } else {
        const float* W = (which == 1 ? Wk : Wv) + moff;
        const float* B = (which == 1 ? bk : bv) + boff;
        const float* R = (which == 1 ? a_rel : m_rel) + (size_t)(l * NT + t) * (HH * DD * DD);
        for (int i = n; i < HH * DD * DD; i += 128) {
            int h = i >> 10;
            float sc = (which == 1) ? p_rel[(l * NT + t) * HH + h] * 0.17677669529663687f : 1.0f;
            sA[i] = R[i] * sc;
        }
        __syncthreads();
        int h = n >> 5, f = n & 31;
        #pragma unroll
        for (int kl = 0; kl < 16; kl++) {
            int k = ks * 16 + kl;
            const float* wr = W + (size_t)k * CC + h * DD;
            const float* ar = sA + h * DD * DD + f;
            float s = 0.f;
            #pragma unroll 8
            for (int d = 0; d < DD; d++) s += wr[d] * ar[d * DD];
            sCol[kl][n] = s;
        }
        if (ks == 0) {
            const float* br = B + h * DD;
            const float* ar = sA + h * DD * DD + f;
            float s = 0.f;
            #pragma unroll 8
            for (int d = 0; d < DD; d++) s += br[d] * ar[d * DD];
            g_bias[widx][n] = s;
        }
    }
    __syncthreads();

    int l32 = n & 31, quad = n >> 5;
    int g = l32 >> 2, tt = l32 & 3;
    #pragma unroll
    for (int jj = 0; jj < 4; jj++) {
        int j = jj * 4 + quad;
        int col = j * 8 + g;
        int k0 = tt * 2;          // local k within this ks chunk
        uint4 frag;
        uint32_t lo0, lo1;
        split2(sCol[k0][col],     sCol[k0 + 1][col], frag.x, lo0);
        split2(sCol[k0 + 8][col], sCol[k0 + 9][col], frag.y, lo1);
        frag.z = lo0; frag.w = lo1;
        g_Wf[widx][(ks * 16 + j) * 32 + l32] = frag;
    }
}

// ---------------- shared mma core: 128x128x128 tile, X hi/lo in smem, W from L1 ----
// warp tile 32x64: 4 M-warps x 2 N-warps. three=1: 3-term split; 0: X-hi only (Q/K).
#define OFF_XHI 0                    // 128 rows * 272B
#define OFF_XLO 34816
#define SMEM_G  69632                // 2 CTAs/SM

__device__ __forceinline__ void mma_tile(uint32_t ah_base, uint32_t al_base,
                                         const uint4* __restrict__ wf, int jbase,
                                         float acc[2][8][4], int three)
{
    #pragma unroll
    for (int mt = 0; mt < 2; mt++)
        #pragma unroll
        for (int nt = 0; nt < 8; nt++)
            #pragma unroll
            for (int r = 0; r < 4; r++) acc[mt][nt][r] = 0.f;
    #pragma unroll
    for (int ks = 0; ks < 8; ks++) {
        uint32_t ah[2][4], al[2][4];
        ldsm4(ah[0], ah_base + ks * 32);
        ldsm4(ah[1], ah_base + 16 * 272 + ks * 32);
        if (three) {
            ldsm4(al[0], al_base + ks * 32);
            ldsm4(al[1], al_base + 16 * 272 + ks * 32);
        }
        #pragma unroll
        for (int nt = 0; nt < 8; nt++) {
            uint4 b = __ldg(&wf[(ks * 16 + jbase + nt) * 32 + lane_id()]);
            #pragma unroll
            for (int mt = 0; mt < 2; mt++) {
                mma_bf16(acc[mt][nt], ah[mt], b.x, b.y);              // hi*hi
                if (three) mma_bf16(acc[mt][nt], al[mt], b.x, b.y);   // lo*hi
                mma_bf16(acc[mt][nt], ah[mt], b.z, b.w);              // hi*lo
            }
        }
    }
}

// ---------------- QKV GEMM: one matrix per blockIdx.y, BM=128 ----------------------
// Q (mat 0) and K (mat 1): 2-term MMA, bf16 output. V (mat 2): 3-term fp32.
__global__ void __launch_bounds__(256, 2)
gemm_qkv(const float* __restrict__ Xbase, int l)
{
    extern __shared__ char smem[];
    uint32_t sb = smem_u32(smem);
    int tid = threadIdx.x, wid = tid >> 5, lane = tid & 31;

    int which = blockIdx.y;
    int t = which / 3, mat = which % 3;
    int three = (mat == 2);
    const float* X = Xbase + (size_t)t * NN * CC;
    const uint4* __restrict__ wf = g_Wf[l * 8 + which];
    const float* __restrict__ bias = g_bias[l * 8 + which];
    int row0 = blockIdx.x * 128;

    // load X tile (128 rows), split into bf16 hi/lo padded tiles (row stride 272B)
    {
        uint32_t* xh = (uint32_t*)(smem + OFF_XHI);
        uint32_t* xl = (uint32_t*)(smem + OFF_XLO);
        #pragma unroll
        for (int i = 0; i < 16; i++) {
            int idx = tid + i * 256;          // 0..4095 float4s
            int m = idx >> 5, c4 = (idx & 31) * 4;
            int gm = row0 + m;
            float4 v = make_float4(0.f, 0.f, 0.f, 0.f);
            if (gm < NN) v = *(const float4*)(X + (size_t)gm * CC + c4);
            uint32_t h0, l0, h1, l1;
            split2(v.x, v.y, h0, l0);
            split2(v.z, v.w, h1, l1);
            int off = m * 68 + (c4 >> 1);
            *(uint2*)(xh + off) = make_uint2(h0, h1);
            if (three) *(uint2*)(xl + off) = make_uint2(l0, l1);
        }
    }
    __syncthreads();

    int warpM = (wid & 3) * 32;
    int jbase = (wid >> 2) * 8;
    uint32_t xrow = (uint32_t)(warpM + (lane & 15)) * 272 + (uint32_t)(lane >> 4) * 16;
    float acc[2][8][4];
    mma_tile(sb + OFF_XHI + xrow, sb + OFF_XLO + xrow, wf, jbase, acc, three);

    int g = lane >> 2, tt = lane & 3;
    if (mat < 2) {
        __nv_bfloat16* Yh = (mat == 0) ? g_qh[t] : g_kh[t];
        #pragma unroll
        for (int mt = 0; mt < 2; mt++) {
            int r0 = row0 + warpM + mt * 16 + g;
            #pragma unroll
            for (int nt = 0; nt < 8; nt++) {
                int c = (jbase + nt) * 8 + tt * 2;
                float b0 = __ldg(&bias[c]), b1 = __ldg(&bias[c + 1]);
                if (r0 < NN)
                    *(uint32_t*)(Yh + (size_t)r0 * CC + c) =
                        pack_bf16(acc[mt][nt][0] + b0, acc[mt][nt][1] + b1);
                if (r0 + 8 < NN)
                    *(uint32_t*)(Yh + (size_t)(r0 + 8) * CC + c) =
                        pack_bf16(acc[mt][nt][2] + b0, acc[mt][nt][3] + b1);
            }
        }
    } else {
        float* Y = g_v[t];
        #pragma unroll
        for (int mt = 0; mt < 2; mt++) {
            int r0 = row0 + warpM + mt * 16 + g;
            #pragma unroll
            for (int nt = 0; nt < 8; nt++) {
                int c = (jbase + nt) * 8 + tt * 2;
                float b0 = __ldg(&bias[c]), b1 = __ldg(&bias[c + 1]);
                if (r0 < NN)
                    *(float2*)(Y + (size_t)r0 * CC + c) =
                        make_float2(acc[mt][nt][0] + b0, acc[mt][nt][1] + b1);
                if (r0 + 8 < NN)
                    *(float2*)(Y + (size_t)(r0 + 8) * CC + c) =
                        make_float2(acc[mt][nt][2] + b0, acc[mt][nt][3] + b1);
            }
        }
    }
}

// ---------------- fused Wa GEMM + gated skip + LayerNorm + ReLU, BM=128 ------------
__global__ void __launch_bounds__(256, 2)
wa_ln(const float* __restrict__ xin_base, float* __restrict__ dout,
      const float* __restrict__ skip, const float* __restrict__ lng,
      const float* __restrict__ lnb, int l)
{
    extern __shared__ char smem[];
    uint32_t sb = smem_u32(smem);
    int tid = threadIdx.x, wid = tid >> 5, lane = tid & 31;
    int t = blockIdx.y;
    const float* X = g_agg[t];
    const float* den = g_den[t];
    const uint4* __restrict__ wf = g_Wf[l * 8 + 6 + t];
    const float* __restrict__ bias = g_bias[l * 8 + 6 + t];
    int row0 = blockIdx.x * 128;

    {
        uint32_t* xh = (uint32_t*)(smem + OFF_XHI);
        uint32_t* xl = (uint32_t*)(smem + OFF_XLO);
        #pragma unroll
        for (int i = 0; i < 16; i++) {
            int idx = tid + i * 256;
            int m = idx >> 5, c4 = (idx & 31) * 4;
            int gm = row0 + m;
            float4 v = make_float4(0.f, 0.f, 0.f, 0.f);
            if (gm < NN) {
                v = *(const float4*)(X + (size_t)gm * CC + c4);
                float invd = __fdividef(1.f, den[(size_t)gm * HH + (c4 >> 5)] + 1e-16f);
                v.x = gelu_fast(v.x * invd); v.y = gelu_fast(v.y * invd);
                v.z = gelu_fast(v.z * invd); v.w = gelu_fast(v.w * invd);
            }
            uint32_t h0, l0, h1, l1;
            split2(v.x, v.y, h0, l0);
            split2(v.z, v.w, h1, l1);
            int off = m * 68 + (c4 >> 1);
            *(uint2*)(xh + off) = make_uint2(h0, h1);
            *(uint2*)(xl + off) = make_uint2(l0, l1);
        }
    }
    __syncthreads();

    int warpM = (wid & 3) * 32;
    int jbase = (wid >> 2) * 8;
    uint32_t xrow = (uint32_t)(warpM + (lane & 15)) * 272 + (uint32_t)(lane >> 4) * 16;
    float acc[2][8][4];
    mma_tile(sb + OFF_XHI + xrow, sb + OFF_XLO + xrow, wf, jbase, acc, 1);
    __syncthreads();   // all LDSM complete -> smem reusable for o staging

    // stage o = acc + bias into smem [128][128] fp32 (64KB fits the 69.6KB X region)
    float* sO = (float*)smem;
    {
        int g = lane >> 2, tt = lane & 3;
        #pragma unroll
        for (int mt = 0; mt < 2; mt++) {
            int rl = warpM + mt * 16 + g;
            #pragma unroll
            for (int nt = 0; nt < 8; nt++) {
                int c = (jbase + nt) * 8 + tt * 2;
                float b0 = __ldg(&bias[c]), b1 = __ldg(&bias[c + 1]);
                *(float2*)(sO + rl * CC + c)       = make_float2(acc[mt][nt][0] + b0, acc[mt][nt][1] + b1);
                *(float2*)(sO + (rl + 8) * CC + c) = make_float2(acc[mt][nt][2] + b0, acc[mt][nt][3] + b1);
            }
        }
    }
    __syncthreads();

    // per-row: skip-mix + LayerNorm + ReLU (warp per row, 16 rows per warp)
    const float* xin = xin_base + (size_t)t * NN * CC;
    float beta = __fdividef(1.f, 1.f + __expf(-skip[l * NT + t]));
    float4 g4 = ((const float4*)(lng + (size_t)(l * NT + t) * CC))[lane];
    float4 b4 = ((const float4*)(lnb + (size_t)(l * NT + t) * CC))[lane];

    #pragma unroll
    for (int it = 0; it < 16; it++) {
        int rl = wid * 16 + it;
        int gm = row0 + rl;
        if (gm >= NN) break;
        float4 ov = ((const float4*)(sO + rl * CC))[lane];
        float4 xv = ((const float4*)(xin + (size_t)gm * CC))[lane];
        float4 v;
        v.x = beta * ov.x + (1.f - beta) * xv.x;
        v.y = beta * ov.y + (1.f - beta) * xv.y;
        v.z = beta * ov.z + (1.f - beta) * xv.z;
        v.w = beta * ov.w + (1.f - beta) * xv.w;

        float s  = v.x + v.y + v.z + v.w;
        float sq = v.x * v.x + v.y * v.y + v.z * v.z + v.w * v.w;
        #pragma unroll
        for (int m = 16; m; m >>= 1) {
            s  += __shfl_xor_sync(0xffffffffu, s,  m);
            sq += __shfl_xor_sync(0xffffffffu, sq, m);
        }
        float mu  = s * (1.f / 128.f);
        float var = sq * (1.f / 128.f) - mu * mu;
        float inv = rsqrtf(var + 1e-5f);

        float4 y;
        y.x = fmaxf((v.x - mu) * inv * g4.x + b4.x, 0.f);
        y.y = fmaxf((v.y - mu) * inv * g4.y + b4.y, 0.f);
        y.z = fmaxf((v.z - mu) * inv * g4.z + b4.z, 0.f);
        y.w = fmaxf((v.w - mu) * inv * g4.w + b4.w, 0.f);
        ((float4*)(g_xb[t] + (size_t)gm * CC))[lane] = y;
        if (dout != nullptr && t == 0)
            ((float4*)(dout + (size_t)gm * CC))[lane] = y;
    }
}

// ---------------- CSR build (once per call) ----------------------------------------
__global__ void hist_k(const int* __restrict__ ei)
{
    int e = blockIdx.y;
    int id = blockIdx.x * 256 + threadIdx.x;
    if (id >= EE) return;
    int di = ei[(size_t)(e * 2 + 1) * EE + id];
    atomicAdd(&g_cnt[e][di], 1);
}

// one block (1024 threads) per edge type: exclusive scan of g_cnt -> g_off.
// Also resets g_cnt to 0 for the scatter pass.
__global__ void scan_k()
{
    const int CH = 49;   // 1024*49 = 50176 >= NN
    int e = blockIdx.x, tid = threadIdx.x;
    int base = tid * CH;
    int s = 0;
    for (int i = 0; i < CH; i++) {
        int idx = base + i;
        if (idx < NN) s += g_cnt[e][idx];
    }
    __shared__ int sm[1024];
    sm[tid] = s;
    __syncthreads();
    for (int off = 1; off < 1024; off <<= 1) {
        int v = (tid >= off) ? sm[tid - off] : 0;
        __syncthreads();
        sm[tid] += v;
        __syncthreads();
    }
    int run = sm[tid] - s;   // exclusive prefix
    for (int i = 0; i < CH; i++) {
        int idx = base + i;
        if (idx < NN) {
            g_off[e][idx] = run;
            run += g_cnt[e][idx];
            g_cnt[e][idx] = 0;
        }
    }
    if (tid == 1023) g_off[e][NN] = EE;
}

__global__ void scatter_k(const int* __restrict__ ei)
{
    int e = blockIdx.y;
    int id = blockIdx.x * 256 + threadIdx.x;
    if (id >= EE) return;
    int si = ei[(size_t)(e * 2 + 0) * EE + id];
    int di = ei[(size_t)(e * 2 + 1) * EE + id];
    int pos = g_off[e][di] + atomicAdd(&g_cnt[e][di], 1);
    g_csr[e][pos] = si;
}

// ---------------- edge aggregation: warp per destination, bf16 q/k gathers ---------
__global__ void edge_agg_csr()
{
    int e = blockIdx.y, st = e, dt = 1 - e;
    int n = blockIdx.x * 8 + (threadIdx.x >> 5);
    if (n >= NN) return;
    int lane = threadIdx.x & 31;
    int beg = g_off[e][n], end = g_off[e][n + 1];

    float4 qv;
    {
        uint2 qw = *(const uint2*)(g_qh[dt] + (size_t)n * CC + lane * 4);
        float2 f0 = __bfloat1622float2(*reinterpret_cast<__nv_bfloat162*>(&qw.x));
        float2 f1 = __bfloat1622float2(*reinterpret_cast<__nv_bfloat162*>(&qw.y));
        qv = make_float4(f0.x, f0.y, f1.x, f1.y);
    }
    float4 acc = make_float4(0.f, 0.f, 0.f, 0.f);
    float den = 0.f;

    if (beg < end) {
        int si = g_csr[e][beg];
        uint2 kw = *(const uint2*)(g_kh[st] + (size_t)si * CC + lane * 4);
        float4 vv = ((const float4*)(g_v[st] + (size_t)si * CC))[lane];
        for (int j = beg; j < end; j++) {
            int sin = (j + 1 < end) ? g_csr[e][j + 1] : si;
            uint2 kn = *(const uint2*)(g_kh[st] + (size_t)sin * CC + lane * 4);
            float4 vn = ((const float4*)(g_v[st] + (size_t)sin * CC))[lane];
            float2 k0 = __bfloat1622float2(*reinterpret_cast<__nv_bfloat162*>(&kw.x));
            float2 k1 = __bfloat1622float2(*reinterpret_cast<__nv_bfloat162*>(&kw.y));
            float s = k0.x * qv.x + k0.y * qv.y + k1.x * qv.z + k1.y * qv.w;
            s += __shfl_xor_sync(0xffffffffu, s, 1);
            s += __shfl_xor_sync(0xffffffffu, s, 2);
            s += __shfl_xor_sync(0xffffffffu, s, 4);
            float a = __expf(s);
            den += a;
            acc.x += a * vv.x; acc.y += a * vv.y;
            acc.z += a * vv.z; acc.w += a * vv.w;
            kw = kn; vv = vn;
        }
    }
    ((float4*)(g_agg[dt] + (size_t)n * CC))[lane] = acc;
    if ((lane & 7) == 0)
        g_den[dt][(size_t)n * HH + (lane >> 3)] = den;
}

// ---------------- host orchestration ------------------------------------------------
extern "C" void kernel_launch(void* const* d_in, const int* in_sizes, int n_in,
                              void* d_out, int out_size)
{
    const float* x     = (const float*)d_in[0];
    const int*   ei    = (const int*)d_in[1];   // int32 on device (JAX x64 disabled)
    const float* Wk    = (const float*)d_in[2];
    const float* bk    = (const float*)d_in[3];
    const float* Wq    = (const float*)d_in[4];
    const float* bq    = (const float*)d_in[5];
    const float* Wv    = (const float*)d_in[6];
    const float* bv    = (const float*)d_in[7];
    const float* Wa    = (const float*)d_in[8];
    const float* ba    = (const float*)d_in[9];
    const float* skip  = (const float*)d_in[10];
    const float* a_rel = (const float*)d_in[11];
    const float* m_rel = (const float*)d_in[12];
    const float* p_rel = (const float*)d_in[13];
    const float* ln_g  = (const float*)d_in[14];
    const float* ln_b  = (const float*)d_in[15];
    float* out = (float*)d_out;

    void* pxb;
    cudaGetSymbolAddress(&pxb, g_xb);

    cudaFuncSetAttribute(gemm_qkv, cudaFuncAttributeMaxDynamicSharedMemorySize, SMEM_G);
    cudaFuncSetAttribute(wa_ln, cudaFuncAttributeMaxDynamicSharedMemorySize, SMEM_G);

    dim3 qkv_grid(NTILES128, 6);
    dim3 wa_grid(NTILES128, 2);
    dim3 ed_grid((EE + 255) / 256, 2);
    dim3 agg_grid((NN + 7) / 8, 2);

    // ---- CSR build + both layers' weight prep (no memsets: prep zeroes g_cnt) ----
    prep_weights<<<dim3(2, 4, 16), 128>>>(Wk, bk, Wv, bv, Wq, bq, Wa, ba,
                                          a_rel, m_rel, p_rel);
    hist_k<<<ed_grid, 256>>>(ei);
    scan_k<<<2, 1024>>>();
    scatter_k<<<ed_grid, 256>>>(ei);

    for (int l = 0; l < 2; l++) {
        const float* xin = (l == 0) ? x : (const float*)pxb;

        gemm_qkv<<<qkv_grid, 256, SMEM_G>>>(xin, l);

        edge_agg_csr<<<agg_grid, 256>>>();

        wa_ln<<<wa_grid, 256, SMEM_G>>>(xin, (l == 1) ? out : nullptr,
                                        skip, ln_g, ln_b, l);
    }
}

// round 17
// speedup vs baseline: 1.1672x; 1.0704x over previous
#include <cuda_runtime.h>
#include <cuda_bf16.h>
#include <math.h>
#include <stdint.h>

#define NT 2
#define NN 50000
#define EE 400000
#define CC 128
#define HH 4
#define DD 32
#define NTILES128 391   // ceil(50000/128)

// ---------------- device scratch (allocation-free: static globals) ----------------
__device__ __nv_bfloat16 g_qh[NT][(size_t)NN*CC];   // q in bf16 (logit path only)
__device__ __nv_bfloat16 g_kh[NT][(size_t)NN*CC];   // k_rel in bf16 (logit path only)
__device__ __nv_bfloat16 g_vh[NT][(size_t)NN*CC];   // v_rel in bf16 (agg in fp32)
__device__ float g_agg[NT][(size_t)NN*CC];   // UNNORMALIZED sum of a*v (fp32)
__device__ float g_xb [NT][(size_t)NN*CC];   // layer output ping buffer
__device__ float g_den[NT][(size_t)NN*HH];
// CSR by destination, per edge type (built once per call)
__device__ int g_off[NT][NN + 1];
__device__ int g_csr[NT][EE];
__device__ int g_cnt[NT][NN];
// W in mma B-fragment order, BOTH layers: widx = l*8 + (t*3+{Q,K,V} | 6+t for Wa)
__device__ uint4 g_Wf  [16][4096];
__device__ float g_bias[16][CC];

// ---------------- small helpers ----------------------------------------------------
__device__ __forceinline__ int lane_id() { return threadIdx.x & 31; }

__device__ __forceinline__ uint32_t smem_u32(const void* p) {
    uint32_t a;
    asm("{ .reg .u64 t; cvta.to.shared.u64 t, %1; cvt.u32.u64 %0, t; }" : "=r"(a) : "l"(p));
    return a;
}
// gelu(tanh approx) == v * sigmoid(2c(v + 0.044715 v^3)) — exact identity, MUFU-cheap
__device__ __forceinline__ float gelu_fast(float v) {
    float z = 1.5957691216057308f * (v + 0.044715f * v * v * v);
    return __fdividef(v, 1.0f + __expf(-z));
}
// split two floats into packed bf16x2 hi and lo words (elem0 in low half)
__device__ __forceinline__ void split2(float v0, float v1, uint32_t& hi, uint32_t& lo) {
    __nv_bfloat16 h0 = __float2bfloat16_rn(v0), h1 = __float2bfloat16_rn(v1);
    __nv_bfloat16 l0 = __float2bfloat16_rn(v0 - __bfloat162float(h0));
    __nv_bfloat16 l1 = __float2bfloat16_rn(v1 - __bfloat162float(h1));
    __nv_bfloat162 H = __halves2bfloat162(h0, h1);
    __nv_bfloat162 L = __halves2bfloat162(l0, l1);
    hi = *(uint32_t*)&H; lo = *(uint32_t*)&L;
}
__device__ __forceinline__ uint32_t pack_bf16(float v0, float v1) {
    __nv_bfloat162 h = __halves2bfloat162(__float2bfloat16_rn(v0), __float2bfloat16_rn(v1));
    return *(uint32_t*)&h;
}
__device__ __forceinline__ void mma_bf16(float* d, const uint32_t* a, uint32_t b0, uint32_t b1) {
    asm volatile("mma.sync.aligned.m16n8k16.row.col.f32.bf16.bf16.f32 "
        "{%0,%1,%2,%3}, {%4,%5,%6,%7}, {%8,%9}, {%0,%1,%2,%3};"
        : "+f"(d[0]), "+f"(d[1]), "+f"(d[2]), "+f"(d[3])
        : "r"(a[0]), "r"(a[1]), "r"(a[2]), "r"(a[3]), "r"(b0), "r"(b1));
}
__device__ __forceinline__ void ldsm4(uint32_t* r, uint32_t addr) {
    asm volatile("ldmatrix.sync.aligned.m8n8.x4.shared.b16 {%0,%1,%2,%3}, [%4];"
        : "=r"(r[0]), "=r"(r[1]), "=r"(r[2]), "=r"(r[3]) : "r"(addr));
}

// ---------------- prep: fold + split + fragment-order weights (both layers) --------
// grid (t=2, which=4, 16 = l*8 + ks). 128 threads. Also zeroes g_cnt.
__global__ void prep_weights(const float* __restrict__ Wk, const float* __restrict__ bk,
                             const float* __restrict__ Wv, const float* __restrict__ bv,
                             const float* __restrict__ Wq, const float* __restrict__ bq,
                             const float* __restrict__ Wa, const float* __restrict__ ba,
                             const float* __restrict__ a_rel, const float* __restrict__ m_rel,
                             const float* __restrict__ p_rel)
{
    __shared__ float sA[HH * DD * DD];   // 16KB [h][d][f]
    __shared__ float sCol[16][CC];       // 8KB  local k-slice of folded W

    // zero g_cnt (replaces a memset launch); 128 blocks x 128 threads
    {
        int gtid = (((blockIdx.z * 4) + blockIdx.y) * 2 + blockIdx.x) * 128 + threadIdx.x;
        for (int i = gtid; i < NT * NN; i += 16384) ((int*)g_cnt)[i] = 0;
    }

    int t = blockIdx.x, which = blockIdx.y;
    int l = blockIdx.z >> 3, ks = blockIdx.z & 7;
    int widx = l * 8 + ((which == 3) ? (6 + t) : (t * 3 + which));
    int n = threadIdx.x;                 // output column
    size_t moff = (size_t)(l * NT + t) * CC * CC;
    size_t boff = (size_t)(l * NT + t) * CC;

    if (which == 0 || which == 3) {
        const float* W = (which == 0 ? Wq : Wa) + moff;
        const float* B = (which == 0 ? bq : ba) + boff;
        #pragma unroll
        for (int kl = 0; kl < 16; kl++)
            sCol[kl][n] = W[(size_t)(ks * 16 + kl) * CC + n];
        if (ks == 0) g_bias[widx][n] = B[n];
    } else {
        const float* W = (which == 1 ? Wk : Wv) + moff;
        const float* B = (which == 1 ? bk : bv) + boff;
        const float* R = (which == 1 ? a_rel : m_rel) + (size_t)(l * NT + t) * (HH * DD * DD);
        for (int i = n; i < HH * DD * DD; i += 128) {
            int h = i >> 10;
            float sc = (which == 1) ? p_rel[(l * NT + t) * HH + h] * 0.17677669529663687f : 1.0f;
            sA[i] = R[i] * sc;
        }
        __syncthreads();
        int h = n >> 5, f = n & 31;
        #pragma unroll
        for (int kl = 0; kl < 16; kl++) {
            int k = ks * 16 + kl;
            const float* wr = W + (size_t)k * CC + h * DD;
            const float* ar = sA + h * DD * DD + f;
            float s = 0.f;
            #pragma unroll 8
            for (int d = 0; d < DD; d++) s += wr[d] * ar[d * DD];
            sCol[kl][n] = s;
        }
        if (ks == 0) {
            const float* br = B + h * DD;
            const float* ar = sA + h * DD * DD + f;
            float s = 0.f;
            #pragma unroll 8
            for (int d = 0; d < DD; d++) s += br[d] * ar[d * DD];
            g_bias[widx][n] = s;
        }
    }
    __syncthreads();

    int l32 = n & 31, quad = n >> 5;
    int g = l32 >> 2, tt = l32 & 3;
    #pragma unroll
    for (int jj = 0; jj < 4; jj++) {
        int j = jj * 4 + quad;
        int col = j * 8 + g;
        int k0 = tt * 2;          // local k within this ks chunk
        uint4 frag;
        uint32_t lo0, lo1;
        split2(sCol[k0][col],     sCol[k0 + 1][col], frag.x, lo0);
        split2(sCol[k0 + 8][col], sCol[k0 + 9][col], frag.y, lo1);
        frag.z = lo0; frag.w = lo1;
        g_Wf[widx][(ks * 16 + j) * 32 + l32] = frag;
    }
}

// ---------------- shared mma core: 128x128x128 tile, X hi/lo in smem, W from L1 ----
// warp tile 32x64: 4 M-warps x 2 N-warps. three=1: 3-term split; 0: X-hi only.
#define OFF_XHI 0                    // 128 rows * 272B
#define OFF_XLO 34816
#define SMEM_QKV 34816               // X-hi only
#define SMEM_WA  69632               // X-hi + X-lo

__device__ __forceinline__ void mma_tile(uint32_t ah_base, uint32_t al_base,
                                         const uint4* __restrict__ wf, int jbase,
                                         float acc[2][8][4], int three)
{
    #pragma unroll
    for (int mt = 0; mt < 2; mt++)
        #pragma unroll
        for (int nt = 0; nt < 8; nt++)
            #pragma unroll
            for (int r = 0; r < 4; r++) acc[mt][nt][r] = 0.f;
    #pragma unroll
    for (int ks = 0; ks < 8; ks++) {
        uint32_t ah[2][4], al[2][4];
        ldsm4(ah[0], ah_base + ks * 32);
        ldsm4(ah[1], ah_base + 16 * 272 + ks * 32);
        if (three) {
            ldsm4(al[0], al_base + ks * 32);
            ldsm4(al[1], al_base + 16 * 272 + ks * 32);
        }
        #pragma unroll
        for (int nt = 0; nt < 8; nt++) {
            uint4 b = __ldg(&wf[(ks * 16 + jbase + nt) * 32 + lane_id()]);
            #pragma unroll
            for (int mt = 0; mt < 2; mt++) {
                mma_bf16(acc[mt][nt], ah[mt], b.x, b.y);              // hi*hi
                if (three) mma_bf16(acc[mt][nt], al[mt], b.x, b.y);   // lo*hi
                mma_bf16(acc[mt][nt], ah[mt], b.z, b.w);              // hi*lo
            }
        }
    }
}

// ---------------- QKV GEMM: one matrix per blockIdx.y, BM=128 ----------------------
// All three mats: 2-term MMA (X-hi only), bf16 output.
__global__ void __launch_bounds__(256, 2)
gemm_qkv(const float* __restrict__ Xbase, int l)
{
    extern __shared__ char smem[];
    uint32_t sb = smem_u32(smem);
    int tid = threadIdx.x, wid = tid >> 5, lane = tid & 31;

    int which = blockIdx.y;
    int t = which / 3, mat = which % 3;
    const float* X = Xbase + (size_t)t * NN * CC;
    const uint4* __restrict__ wf = g_Wf[l * 8 + which];
    const float* __restrict__ bias = g_bias[l * 8 + which];
    int row0 = blockIdx.x * 128;

    // load X tile (128 rows), bf16-hi only (row stride 272B)
    {
        uint32_t* xh = (uint32_t*)(smem + OFF_XHI);
        #pragma unroll
        for (int i = 0; i < 16; i++) {
            int idx = tid + i * 256;          // 0..4095 float4s
            int m = idx >> 5, c4 = (idx & 31) * 4;
            int gm = row0 + m;
            float4 v = make_float4(0.f, 0.f, 0.f, 0.f);
            if (gm < NN) v = *(const float4*)(X + (size_t)gm * CC + c4);
            uint32_t h0 = pack_bf16(v.x, v.y);
            uint32_t h1 = pack_bf16(v.z, v.w);
            *(uint2*)(xh + m * 68 + (c4 >> 1)) = make_uint2(h0, h1);
        }
    }
    __syncthreads();

    int warpM = (wid & 3) * 32;
    int jbase = (wid >> 2) * 8;
    uint32_t xrow = (uint32_t)(warpM + (lane & 15)) * 272 + (uint32_t)(lane >> 4) * 16;
    float acc[2][8][4];
    mma_tile(sb + OFF_XHI + xrow, 0, wf, jbase, acc, 0);

    int g = lane >> 2, tt = lane & 3;
    __nv_bfloat16* Yh = (mat == 0) ? g_qh[t] : (mat == 1) ? g_kh[t] : g_vh[t];
    #pragma unroll
    for (int mt = 0; mt < 2; mt++) {
        int r0 = row0 + warpM + mt * 16 + g;
        #pragma unroll
        for (int nt = 0; nt < 8; nt++) {
            int c = (jbase + nt) * 8 + tt * 2;
            float b0 = __ldg(&bias[c]), b1 = __ldg(&bias[c + 1]);
            if (r0 < NN)
                *(uint32_t*)(Yh + (size_t)r0 * CC + c) =
                    pack_bf16(acc[mt][nt][0] + b0, acc[mt][nt][1] + b1);
            if (r0 + 8 < NN)
                *(uint32_t*)(Yh + (size_t)(r0 + 8) * CC + c) =
                    pack_bf16(acc[mt][nt][2] + b0, acc[mt][nt][3] + b1);
        }
    }
}

// ---------------- fused Wa GEMM + gated skip + LayerNorm + ReLU, BM=128 ------------
__global__ void __launch_bounds__(256, 2)
wa_ln(const float* __restrict__ xin_base, float* __restrict__ dout,
      const float* __restrict__ skip, const float* __restrict__ lng,
      const float* __restrict__ lnb, int l)
{
    extern __shared__ char smem[];
    uint32_t sb = smem_u32(smem);
    int tid = threadIdx.x, wid = tid >> 5, lane = tid & 31;
    int t = blockIdx.y;
    const float* X = g_agg[t];
    const float* den = g_den[t];
    const uint4* __restrict__ wf = g_Wf[l * 8 + 6 + t];
    const float* __restrict__ bias = g_bias[l * 8 + 6 + t];
    int row0 = blockIdx.x * 128;

    {
        uint32_t* xh = (uint32_t*)(smem + OFF_XHI);
        uint32_t* xl = (uint32_t*)(smem + OFF_XLO);
        #pragma unroll
        for (int i = 0; i < 16; i++) {
            int idx = tid + i * 256;
            int m = idx >> 5, c4 = (idx & 31) * 4;
            int gm = row0 + m;
            float4 v = make_float4(0.f, 0.f, 0.f, 0.f);
            if (gm < NN) {
                v = *(const float4*)(X + (size_t)gm * CC + c4);
                float invd = __fdividef(1.f, den[(size_t)gm * HH + (c4 >> 5)] + 1e-16f);
                v.x = gelu_fast(v.x * invd); v.y = gelu_fast(v.y * invd);
                v.z = gelu_fast(v.z * invd); v.w = gelu_fast(v.w * invd);
            }
            uint32_t h0, l0, h1, l1;
            split2(v.x, v.y, h0, l0);
            split2(v.z, v.w, h1, l1);
            int off = m * 68 + (c4 >> 1);
            *(uint2*)(xh + off) = make_uint2(h0, h1);
            *(uint2*)(xl + off) = make_uint2(l0, l1);
        }
    }
    __syncthreads();

    int warpM = (wid & 3) * 32;
    int jbase = (wid >> 2) * 8;
    uint32_t xrow = (uint32_t)(warpM + (lane & 15)) * 272 + (uint32_t)(lane >> 4) * 16;
    float acc[2][8][4];
    mma_tile(sb + OFF_XHI + xrow, sb + OFF_XLO + xrow, wf, jbase, acc, 1);
    __syncthreads();   // all LDSM complete -> smem reusable for o staging

    // stage o = acc + bias into smem [128][128] fp32
    float* sO = (float*)smem;
    {
        int g = lane >> 2, tt = lane & 3;
        #pragma unroll
        for (int mt = 0; mt < 2; mt++) {
            int rl = warpM + mt * 16 + g;
            #pragma unroll
            for (int nt = 0; nt < 8; nt++) {
                int c = (jbase + nt) * 8 + tt * 2;
                float b0 = __ldg(&bias[c]), b1 = __ldg(&bias[c + 1]);
                *(float2*)(sO + rl * CC + c)       = make_float2(acc[mt][nt][0] + b0, acc[mt][nt][1] + b1);
                *(float2*)(sO + (rl + 8) * CC + c) = make_float2(acc[mt][nt][2] + b0, acc[mt][nt][3] + b1);
            }
        }
    }
    __syncthreads();

    // per-row: skip-mix + LayerNorm + ReLU (warp per row, 16 rows per warp)
    const float* xin = xin_base + (size_t)t * NN * CC;
    float beta = __fdividef(1.f, 1.f + __expf(-skip[l * NT + t]));
    float4 g4 = ((const float4*)(lng + (size_t)(l * NT + t) * CC))[lane];
    float4 b4 = ((const float4*)(lnb + (size_t)(l * NT + t) * CC))[lane];

    #pragma unroll
    for (int it = 0; it < 16; it++) {
        int rl = wid * 16 + it;
        int gm = row0 + rl;
        if (gm >= NN) break;
        float4 ov = ((const float4*)(sO + rl * CC))[lane];
        float4 xv = ((const float4*)(xin + (size_t)gm * CC))[lane];
        float4 v;
        v.x = beta * ov.x + (1.f - beta) * xv.x;
        v.y = beta * ov.y + (1.f - beta) * xv.y;
        v.z = beta * ov.z + (1.f - beta) * xv.z;
        v.w = beta * ov.w + (1.f - beta) * xv.w;

        float s  = v.x + v.y + v.z + v.w;
        float sq = v.x * v.x + v.y * v.y + v.z * v.z + v.w * v.w;
        #pragma unroll
        for (int m = 16; m; m >>= 1) {
            s  += __shfl_xor_sync(0xffffffffu, s,  m);
            sq += __shfl_xor_sync(0xffffffffu, sq, m);
        }
        float mu  = s * (1.f / 128.f);
        float var = sq * (1.f / 128.f) - mu * mu;
        float inv = rsqrtf(var + 1e-5f);

        float4 y;
        y.x = fmaxf((v.x - mu) * inv * g4.x + b4.x, 0.f);
        y.y = fmaxf((v.y - mu) * inv * g4.y + b4.y, 0.f);
        y.z = fmaxf((v.z - mu) * inv * g4.z + b4.z, 0.f);
        y.w = fmaxf((v.w - mu) * inv * g4.w + b4.w, 0.f);
        ((float4*)(g_xb[t] + (size_t)gm * CC))[lane] = y;
        if (dout != nullptr && t == 0)
            ((float4*)(dout + (size_t)gm * CC))[lane] = y;
    }
}

// ---------------- CSR build (once per call) ----------------------------------------
__global__ void hist_k(const int* __restrict__ ei)
{
    int e = blockIdx.y;
    int id = blockIdx.x * 256 + threadIdx.x;
    if (id >= EE) return;
    int di = ei[(size_t)(e * 2 + 1) * EE + id];
    atomicAdd(&g_cnt[e][di], 1);
}

// one block (1024 threads) per edge type: exclusive scan of g_cnt -> g_off.
// Also resets g_cnt to 0 for the scatter pass.
__global__ void scan_k()
{
    const int CH = 49;   // 1024*49 = 50176 >= NN
    int e = blockIdx.x, tid = threadIdx.x;
    int base = tid * CH;
    int s = 0;
    for (int i = 0; i < CH; i++) {
        int idx = base + i;
        if (idx < NN) s += g_cnt[e][idx];
    }
    __shared__ int sm[1024];
    sm[tid] = s;
    __syncthreads();
    for (int off = 1; off < 1024; off <<= 1) {
        int v = (tid >= off) ? sm[tid - off] : 0;
        __syncthreads();
        sm[tid] += v;
        __syncthreads();
    }
    int run = sm[tid] - s;   // exclusive prefix
    for (int i = 0; i < CH; i++) {
        int idx = base + i;
        if (idx < NN) {
            g_off[e][idx] = run;
            run += g_cnt[e][idx];
            g_cnt[e][idx] = 0;
        }
    }
    if (tid == 1023) g_off[e][NN] = EE;
}

__global__ void scatter_k(const int* __restrict__ ei)
{
    int e = blockIdx.y;
    int id = blockIdx.x * 256 + threadIdx.x;
    if (id >= EE) return;
    int si = ei[(size_t)(e * 2 + 0) * EE + id];
    int di = ei[(size_t)(e * 2 + 1) * EE + id];
    int pos = g_off[e][di] + atomicAdd(&g_cnt[e][di], 1);
    g_csr[e][pos] = si;
}

// ---------------- edge aggregation: warp per destination, bf16 q/k/v gathers -------
__global__ void edge_agg_csr()
{
    int e = blockIdx.y, st = e, dt = 1 - e;
    int n = blockIdx.x * 8 + (threadIdx.x >> 5);
    if (n >= NN) return;
    int lane = threadIdx.x & 31;
    int beg = g_off[e][n], end = g_off[e][n + 1];

    float4 qv;
    {
        uint2 qw = *(const uint2*)(g_qh[dt] + (size_t)n * CC + lane * 4);
        float2 f0 = __bfloat1622float2(*reinterpret_cast<__nv_bfloat162*>(&qw.x));
        float2 f1 = __bfloat1622float2(*reinterpret_cast<__nv_bfloat162*>(&qw.y));
        qv = make_float4(f0.x, f0.y, f1.x, f1.y);
    }
    float4 acc = make_float4(0.f, 0.f, 0.f, 0.f);
    float den = 0.f;

    if (beg < end) {
        int si = g_csr[e][beg];
        uint2 kw = *(const uint2*)(g_kh[st] + (size_t)si * CC + lane * 4);
        uint2 vw = *(const uint2*)(g_vh[st] + (size_t)si * CC + lane * 4);
        for (int j = beg; j < end; j++) {
            int sin = (j + 1 < end) ? g_csr[e][j + 1] : si;
            uint2 kn = *(const uint2*)(g_kh[st] + (size_t)sin * CC + lane * 4);
            uint2 vn = *(const uint2*)(g_vh[st] + (size_t)sin * CC + lane * 4);
            float2 k0 = __bfloat1622float2(*reinterpret_cast<__nv_bfloat162*>(&kw.x));
            float2 k1 = __bfloat1622float2(*reinterpret_cast<__nv_bfloat162*>(&kw.y));
            float s = k0.x * qv.x + k0.y * qv.y + k1.x * qv.z + k1.y * qv.w;
            s += __shfl_xor_sync(0xffffffffu, s, 1);
            s += __shfl_xor_sync(0xffffffffu, s, 2);
            s += __shfl_xor_sync(0xffffffffu, s, 4);
            float a = __expf(s);
            den += a;
            float2 v0 = __bfloat1622float2(*reinterpret_cast<__nv_bfloat162*>(&vw.x));
            float2 v1 = __bfloat1622float2(*reinterpret_cast<__nv_bfloat162*>(&vw.y));
            acc.x += a * v0.x; acc.y += a * v0.y;
            acc.z += a * v1.x; acc.w += a * v1.y;
            kw = kn; vw = vn;
        }
    }
    ((float4*)(g_agg[dt] + (size_t)n * CC))[lane] = acc;
    if ((lane & 7) == 0)
        g_den[dt][(size_t)n * HH + (lane >> 3)] = den;
}

// ---------------- host orchestration ------------------------------------------------
extern "C" void kernel_launch(void* const* d_in, const int* in_sizes, int n_in,
                              void* d_out, int out_size)
{
    const float* x     = (const float*)d_in[0];
    const int*   ei    = (const int*)d_in[1];   // int32 on device (JAX x64 disabled)
    const float* Wk    = (const float*)d_in[2];
    const float* bk    = (const float*)d_in[3];
    const float* Wq    = (const float*)d_in[4];
    const float* bq    = (const float*)d_in[5];
    const float* Wv    = (const float*)d_in[6];
    const float* bv    = (const float*)d_in[7];
    const float* Wa    = (const float*)d_in[8];
    const float* ba    = (const float*)d_in[9];
    const float* skip  = (const float*)d_in[10];
    const float* a_rel = (const float*)d_in[11];
    const float* m_rel = (const float*)d_in[12];
    const float* p_rel = (const float*)d_in[13];
    const float* ln_g  = (const float*)d_in[14];
    const float* ln_b  = (const float*)d_in[15];
    float* out = (float*)d_out;

    void* pxb;
    cudaGetSymbolAddress(&pxb, g_xb);

    cudaFuncSetAttribute(gemm_qkv, cudaFuncAttributeMaxDynamicSharedMemorySize, SMEM_QKV);
    cudaFuncSetAttribute(wa_ln, cudaFuncAttributeMaxDynamicSharedMemorySize, SMEM_WA);

    dim3 qkv_grid(NTILES128, 6);
    dim3 wa_grid(NTILES128, 2);
    dim3 ed_grid((EE + 255) / 256, 2);
    dim3 agg_grid((NN + 7) / 8, 2);

    // ---- CSR build + both layers' weight prep (no memsets: prep zeroes g_cnt) ----
    prep_weights<<<dim3(2, 4, 16), 128>>>(Wk, bk, Wv, bv, Wq, bq, Wa, ba,
                                          a_rel, m_rel, p_rel);
    hist_k<<<ed_grid, 256>>>(ei);
    scan_k<<<2, 1024>>>();
    scatter_k<<<ed_grid, 256>>>(ei);

    for (int l = 0; l < 2; l++) {
        const float* xin = (l == 0) ? x : (const float*)pxb;

        gemm_qkv<<<qkv_grid, 256, SMEM_QKV>>>(xin, l);

        edge_agg_csr<<<agg_grid, 256>>>();

        wa_ln<<<wa_grid, 256, SMEM_WA>>>(xin, (l == 1) ? out : nullptr,
                                         skip, ln_g, ln_b, l);
    }
}